// round 8
// baseline (speedup 1.0000x reference)
#include <cuda_runtime.h>
#include <cuda_bf16.h>
#include <stdint.h>
#include <stddef.h>
#include <math.h>

#define BATCH 4
#define T     2048
#define D     1024
#define MT    (BATCH * T)   // 8192
#define KE3   3072          // 3*D split-extended K (qkv, scores)

// CTA tile 128x128, 8 warps (2M x 4N), warp tile 64x32, BK=32, 2-stage cp.async
#define TM 128
#define TN 128
#define BK 32
#define ASTR 40     // 32 + 8 pad (elems): 80B rows (16B-aligned), conflict-free ldmatrix
#define B2STR 136   // 128 + 8 pad (elems): 272B rows, for [k][n] V tiles
#define STG_ELEMS (TM * ASTR)   // 5120 elems = 10240 B per tile per stage

// ------------------------- device scratch ---------------------------------
__device__ __nv_bfloat16 g_Eext[(size_t)MT * KE3];          // A-role [hi|lo|hi]
__device__ __nv_bfloat16 g_WText[(size_t)3 * D * KE3];      // [n][k] B-role [hi|hi|lo]
__device__ __nv_bfloat16 g_Qext[(size_t)MT * KE3];          // A-role [hi|lo|hi]
__device__ __nv_bfloat16 g_Kext[(size_t)MT * KE3];          // B-role [hi|hi|lo]
__device__ __nv_bfloat16 g_Vext[(size_t)BATCH * 3 * T * D]; // [b][seg][t][d], seg=[hi,hi,lo]
__device__ float         g_S[(size_t)BATCH * T * T];        // fp32 scores
__device__ __nv_bfloat16 g_Sext[(size_t)BATCH * T * 3 * T]; // A-role [hi|lo|hi] along keys

// ------------------------- helpers ------------------------------------
__device__ __forceinline__ uint32_t smem_u32(const void* p) {
    uint32_t a;
    asm("{ .reg .u64 t; cvta.to.shared.u64 t, %1; cvt.u32.u64 %0, t; }" : "=r"(a) : "l"(p));
    return a;
}
__device__ __forceinline__ void cpa16(uint32_t s, const void* g) {
    asm volatile("cp.async.cg.shared.global [%0], [%1], 16;" :: "r"(s), "l"(g));
}
__device__ __forceinline__ void cpa_commit() {
    asm volatile("cp.async.commit_group;" ::: "memory");
}
__device__ __forceinline__ void ldsm_x4(uint32_t& r0, uint32_t& r1, uint32_t& r2, uint32_t& r3,
                                        uint32_t addr) {
    asm volatile("ldmatrix.sync.aligned.m8n8.x4.shared.b16 {%0,%1,%2,%3}, [%4];"
                 : "=r"(r0), "=r"(r1), "=r"(r2), "=r"(r3) : "r"(addr));
}
__device__ __forceinline__ void ldsm_x4_t(uint32_t& r0, uint32_t& r1, uint32_t& r2, uint32_t& r3,
                                          uint32_t addr) {
    asm volatile("ldmatrix.sync.aligned.m8n8.x4.trans.shared.b16 {%0,%1,%2,%3}, [%4];"
                 : "=r"(r0), "=r"(r1), "=r"(r2), "=r"(r3) : "r"(addr));
}
__device__ __forceinline__ void mma_bf16(float* c, const uint32_t* a, const uint32_t* b) {
    asm volatile("mma.sync.aligned.m16n8k16.row.col.f32.bf16.bf16.f32 "
                 "{%0,%1,%2,%3}, {%4,%5,%6,%7}, {%8,%9}, {%0,%1,%2,%3};"
                 : "+f"(c[0]), "+f"(c[1]), "+f"(c[2]), "+f"(c[3])
                 : "r"(a[0]), "r"(a[1]), "r"(a[2]), "r"(a[3]), "r"(b[0]), "r"(b[1]));
}
__device__ __forceinline__ void bsplit(float x, __nv_bfloat16& h, __nv_bfloat16& l) {
    h = __float2bfloat16(x);
    l = __float2bfloat16(x - __bfloat162float(h));
}
__device__ __forceinline__ __nv_bfloat162 mk2(__nv_bfloat16 a, __nv_bfloat16 b) {
    __nv_bfloat162 v; v.x = a; v.y = b; return v;
}

// ------------------------- conversion kernels ------------------------------
__global__ __launch_bounds__(256)
void convE_kernel(const float* __restrict__ E) {
    int idx = blockIdx.x * 256 + threadIdx.x;   // over MT*D
    int row = idx >> 10, k = idx & 1023;
    __nv_bfloat16 h, l;
    bsplit(E[idx], h, l);
    __nv_bfloat16* p = g_Eext + (size_t)row * KE3;
    p[k] = h; p[D + k] = l; p[2 * D + k] = h;   // A-role [hi, lo, hi]
}

__global__ __launch_bounds__(256)
void convW_kernel(const float* __restrict__ Wk, const float* __restrict__ Wq,
                  const float* __restrict__ Wv) {
    const float* W = (blockIdx.z == 0) ? Wk : (blockIdx.z == 1) ? Wq : Wv;
    __nv_bfloat16* dst = g_WText + (size_t)blockIdx.z * D * KE3;
    __shared__ float tsm[32][33];
    int n0 = blockIdx.x * 32, k0 = blockIdx.y * 32;
    int tx = threadIdx.x, ty = threadIdx.y;
    #pragma unroll
    for (int i = 0; i < 4; i++)
        tsm[ty + 8 * i][tx] = W[(size_t)(k0 + ty + 8 * i) * D + n0 + tx];
    __syncthreads();
    #pragma unroll
    for (int i = 0; i < 4; i++) {
        int n = n0 + ty + 8 * i, k = k0 + tx;
        __nv_bfloat16 h, l;
        bsplit(tsm[tx][ty + 8 * i], h, l);       // = W[k][n]
        __nv_bfloat16* p = dst + (size_t)n * KE3;
        p[k] = h; p[D + k] = h; p[2 * D + k] = l;  // B-role [hi, hi, lo]
    }
}

// ------------------------- unified mma.sync GEMM ---------------------------
// MODE 0: qkv   out = E_ext @ WText[z]^T                grid (8, 64, 3)
// MODE 1: score S[b] = Q_ext @ K_ext^T (/32, causal)    grid (16, 16, 4)
// MODE 2: av    O[b] = S_ext @ V_ext (trans-B, bounded) grid (8, 16, 4)
template <int MODE>
__global__ __launch_bounds__(256, 2)
void gemm_mma(float* __restrict__ outp) {
    __shared__ __nv_bfloat16 As[2][STG_ELEMS];   // 2 x 10240 B
    __shared__ __nv_bfloat16 Bs[2][STG_ELEMS];   // 2 x 10240 B (mode2: 32*B2STR <= STG_ELEMS)

    const int tid = threadIdx.x;
    const int wid = tid >> 5, l = tid & 31;
    const int wm = wid & 1, wn = wid >> 1;          // 2(M) x 4(N) warp grid
    const int warpM = wm * 64, warpN = wn * 32;     // warp tile 64x32
    const int bx = blockIdx.x, by = blockIdx.y, bz = blockIdx.z;
    const int mBase = by * TM, nBase = bx * TN;

    const __nv_bfloat16 *Ag, *Bg;
    int ldk, nIter, nJ;
    if (MODE == 0) {
        Ag = g_Eext; Bg = g_WText + (size_t)bz * D * KE3;
        ldk = KE3; nJ = KE3 / BK; nIter = nJ;
    } else if (MODE == 1) {
        if (bx > by) return;                        // strictly above diagonal
        Ag = g_Qext + (size_t)bz * T * KE3;
        Bg = g_Kext + (size_t)bz * T * KE3;
        ldk = KE3; nJ = KE3 / BK; nIter = nJ;
    } else {
        Ag = g_Sext + (size_t)bz * T * (3 * T);
        Bg = g_Vext + (size_t)bz * (3 * T) * D;
        ldk = 3 * T;
        nJ = ((by + 1) * TM) / BK;                  // causal K bound per segment
        nIter = 3 * nJ;
    }

    float c[4][4][4] = {};

    // ---- async loader addressing ----
    const int aRow = tid >> 2;                 // 0..63
    const int aKc  = (tid & 3) * 8;            // 0,8,16,24
    const int vRow = tid >> 4;                 // 0..15 (mode2 B k rows)
    const int vNc  = (tid & 15) * 8;           // 0..120

    const uint32_t AsU = smem_u32(As), BsU = smem_u32(Bs);

    auto kOff = [&](int it) -> int {
        if (MODE == 2) { int s = it / nJ; return s * T + (it - s * nJ) * BK; }
        return it * BK;
    };
    auto issueLoad = [&](int it) {
        const int buf = it & 1;
        const int ko = kOff(it);
        const uint32_t sAb = AsU + (buf * STG_ELEMS) * 2;
        const uint32_t sBb = BsU + (buf * STG_ELEMS) * 2;
        cpa16(sAb + (aRow * ASTR + aKc) * 2,
              Ag + (size_t)(mBase + aRow) * ldk + ko + aKc);
        cpa16(sAb + ((aRow + 64) * ASTR + aKc) * 2,
              Ag + (size_t)(mBase + aRow + 64) * ldk + ko + aKc);
        if (MODE != 2) {
            cpa16(sBb + (aRow * ASTR + aKc) * 2,
                  Bg + (size_t)(nBase + aRow) * ldk + ko + aKc);
            cpa16(sBb + ((aRow + 64) * ASTR + aKc) * 2,
                  Bg + (size_t)(nBase + aRow + 64) * ldk + ko + aKc);
        } else {
            cpa16(sBb + (vRow * B2STR + vNc) * 2,
                  Bg + (size_t)(ko + vRow) * D + nBase + vNc);
            cpa16(sBb + ((vRow + 16) * B2STR + vNc) * 2,
                  Bg + (size_t)(ko + vRow + 16) * D + nBase + vNc);
        }
        cpa_commit();
    };

    // lane-invariant ldmatrix addressing pieces
    const int aLR = (l & 15), aLC = (l >> 4) * 8;                       // A rows/k
    const int bLR = (l >> 4) * 8 + (l & 7), bLC = ((l >> 3) & 1) * 8;   // B[n][k]
    const int vLR = ((l >> 3) & 1) * 8 + (l & 7), vLC = (l >> 4) * 8;   // B[k][n] trans

    issueLoad(0);

    for (int it = 0; it < nIter; it++) {
        if (it + 1 < nIter) {
            issueLoad(it + 1);
            asm volatile("cp.async.wait_group 1;" ::: "memory");
        } else {
            asm volatile("cp.async.wait_group 0;" ::: "memory");
        }
        __syncthreads();

        const int buf = it & 1;
        const uint32_t sAb = AsU + (buf * STG_ELEMS) * 2;
        const uint32_t sBb = BsU + (buf * STG_ELEMS) * 2;

        #pragma unroll
        for (int ks = 0; ks < 2; ks++) {
            uint32_t a[4][4], b[4][2];
            #pragma unroll
            for (int mi = 0; mi < 4; mi++)
                ldsm_x4(a[mi][0], a[mi][1], a[mi][2], a[mi][3],
                        sAb + ((warpM + mi * 16 + aLR) * ASTR + ks * 16 + aLC) * 2);
            if (MODE != 2) {
                #pragma unroll
                for (int n2 = 0; n2 < 4; n2 += 2)
                    ldsm_x4(b[n2][0], b[n2][1], b[n2 + 1][0], b[n2 + 1][1],
                            sBb + ((warpN + n2 * 8 + bLR) * ASTR + ks * 16 + bLC) * 2);
            } else {
                #pragma unroll
                for (int n2 = 0; n2 < 4; n2 += 2)
                    ldsm_x4_t(b[n2][0], b[n2][1], b[n2 + 1][0], b[n2 + 1][1],
                              sBb + ((ks * 16 + vLR) * B2STR + warpN + n2 * 8 + vLC) * 2);
            }
            #pragma unroll
            for (int mi = 0; mi < 4; mi++)
                #pragma unroll
                for (int ni = 0; ni < 4; ni++)
                    mma_bf16(c[mi][ni], a[mi], b[ni]);
        }
        __syncthreads();   // protect buf before next issueLoad overwrites it
    }

    // ---- epilogue (direct from accumulators) ----
    const int l4 = l >> 2, l2 = (l & 3) * 2;
    #pragma unroll
    for (int mi = 0; mi < 4; mi++) {
        #pragma unroll
        for (int ni = 0; ni < 4; ni++) {
            const int n = nBase + warpN + ni * 8 + l2;
            #pragma unroll
            for (int half = 0; half < 2; half++) {
                const int m = mBase + warpM + mi * 16 + l4 + half * 8;
                float v0 = c[mi][ni][half * 2 + 0];
                float v1 = c[mi][ni][half * 2 + 1];
                if (MODE == 0) {
                    __nv_bfloat16 h0, l0, h1, l1;
                    bsplit(v0, h0, l0); bsplit(v1, h1, l1);
                    if (bz == 1) {        // Q: A-role [hi, lo, hi]
                        __nv_bfloat16* p = g_Qext + (size_t)m * KE3;
                        *(__nv_bfloat162*)(p + n)         = mk2(h0, h1);
                        *(__nv_bfloat162*)(p + D + n)     = mk2(l0, l1);
                        *(__nv_bfloat162*)(p + 2 * D + n) = mk2(h0, h1);
                    } else if (bz == 0) { // K: B-role [hi, hi, lo]
                        __nv_bfloat16* p = g_Kext + (size_t)m * KE3;
                        *(__nv_bfloat162*)(p + n)         = mk2(h0, h1);
                        *(__nv_bfloat162*)(p + D + n)     = mk2(h0, h1);
                        *(__nv_bfloat162*)(p + 2 * D + n) = mk2(l0, l1);
                    } else {              // V: [b][seg][t][d], segs [hi, hi, lo]
                        int bb = m >> 11, t = m & (T - 1);
                        __nv_bfloat16* p = g_Vext + (size_t)bb * 3 * T * D;
                        *(__nv_bfloat162*)(p + (size_t)t * D + n)           = mk2(h0, h1);
                        *(__nv_bfloat162*)(p + (size_t)(T + t) * D + n)     = mk2(h0, h1);
                        *(__nv_bfloat162*)(p + (size_t)(2 * T + t) * D + n) = mk2(l0, l1);
                    }
                } else if (MODE == 1) {
                    float s0 = (n     > m) ? -INFINITY : v0 * 0.03125f;
                    float s1 = (n + 1 > m) ? -INFINITY : v1 * 0.03125f;
                    float* p = g_S + (size_t)bz * T * T + (size_t)m * T + n;
                    p[0] = s0; p[1] = s1;
                } else {
                    float* p = outp + (size_t)bz * T * D + (size_t)m * D + n;
                    p[0] = rintf(v0 * 10000.0f) * 1.0e-4f;
                    p[1] = rintf(v1 * 10000.0f) * 1.0e-4f;
                }
            }
        }
    }
}

// ------------------------- softmax -> split bf16 ---------------------------
__global__ __launch_bounds__(256)
void softmax_kernel() {
    const int r = blockIdx.x;
    const int b = r >> 11, t = r & (T - 1);
    float* row = g_S + (size_t)b * T * T + (size_t)t * T;
    __nv_bfloat16* orow = g_Sext + ((size_t)b * T + t) * (3 * T);
    const int L = ((t >> 7) + 1) << 7;   // ceil to 128-tile

    __shared__ float red[256];
    const int tid = threadIdx.x;

    float m = -INFINITY;
    for (int j = tid; j < L; j += 256) m = fmaxf(m, row[j]);
    red[tid] = m;
    __syncthreads();
    #pragma unroll
    for (int s = 128; s > 0; s >>= 1) {
        if (tid < s) red[tid] = fmaxf(red[tid], red[tid + s]);
        __syncthreads();
    }
    m = red[0];
    __syncthreads();

    float sum = 0.0f;
    for (int j = tid; j < L; j += 256) {
        float e = __expf(row[j] - m);   // exp(-inf)=0 handles the causal mask
        row[j] = e;
        sum += e;
    }
    red[tid] = sum;
    __syncthreads();
    #pragma unroll
    for (int s = 128; s > 0; s >>= 1) {
        if (tid < s) red[tid] += red[tid + s];
        __syncthreads();
    }
    const float inv = 1.0f / red[0];
    __syncthreads();

    for (int j = tid; j < L; j += 256) {
        float w = row[j] * inv;
        __nv_bfloat16 h, l;
        bsplit(w, h, l);
        orow[j] = h; orow[T + j] = l; orow[2 * T + j] = h;   // A-role [hi, lo, hi]
    }
}

// ---------------------------------------------------------------------------
extern "C" void kernel_launch(void* const* d_in, const int* in_sizes, int n_in,
                              void* d_out, int out_size) {
    const float* E  = (const float*)d_in[0];
    const float* Wk = (const float*)d_in[1];
    const float* Wq = (const float*)d_in[2];
    const float* Wv = (const float*)d_in[3];
    float* O = (float*)d_out;

    convE_kernel<<<(MT * D) / 256, 256>>>(E);
    convW_kernel<<<dim3(32, 32, 3), dim3(32, 8)>>>(Wk, Wq, Wv);
    gemm_mma<0><<<dim3(D / TN, MT / TM, 3), 256>>>(O);
    gemm_mma<1><<<dim3(T / TN, T / TM, BATCH), 256>>>(O);
    softmax_kernel<<<MT, 256>>>();
    gemm_mma<2><<<dim3(D / TN, T / TM, BATCH), 256>>>(O);
}

// round 9
// speedup vs baseline: 1.4952x; 1.4952x over previous
#include <cuda_runtime.h>
#include <cuda_bf16.h>
#include <stdint.h>
#include <stddef.h>
#include <math.h>

#define BATCH 4
#define T     2048
#define D     1024
#define MT    (BATCH * T)   // 8192
#define KE3   3072          // 3*D split-extended K (qkv, scores)

// CTA tile 128x128, 8 warps (2M x 4N), warp tile 64x32, BK=32
#define TM 128
#define TN 128
#define BK 32
#define ASTR 40     // 32 + 8 pad (elems): conflict-free ldmatrix
#define B2STR 136   // 128 + 8 pad (elems) for [k][n] V tiles
#define STG_ELEMS (TM * ASTR)   // 5120 elems = 10240 B per tile per stage

// ------------------------- device scratch ---------------------------------
__device__ __nv_bfloat16 g_Eext[(size_t)MT * KE3];          // A-role [hi|lo|hi]
__device__ __nv_bfloat16 g_WText[(size_t)3 * D * KE3];      // [n][k] B-role [hi|hi|lo]
__device__ __nv_bfloat16 g_Qext[(size_t)MT * KE3];          // A-role [hi|lo|hi]
__device__ __nv_bfloat16 g_Kext[(size_t)MT * KE3];          // B-role [hi|hi|lo]
__device__ __nv_bfloat16 g_Vext[(size_t)BATCH * 3 * T * D]; // [b][seg][t][d], seg=[hi,hi,lo]
__device__ float         g_S[(size_t)BATCH * T * T];        // fp32 scores
__device__ __nv_bfloat16 g_Sext[(size_t)BATCH * T * 3 * T]; // A-role [hi|lo|hi] along keys

// ------------------------- helpers ------------------------------------
__device__ __forceinline__ uint32_t smem_u32(const void* p) {
    uint32_t a;
    asm("{ .reg .u64 t; cvta.to.shared.u64 t, %1; cvt.u32.u64 %0, t; }" : "=r"(a) : "l"(p));
    return a;
}
__device__ __forceinline__ void ldsm_x4(uint32_t& r0, uint32_t& r1, uint32_t& r2, uint32_t& r3,
                                        uint32_t addr) {
    asm volatile("ldmatrix.sync.aligned.m8n8.x4.shared.b16 {%0,%1,%2,%3}, [%4];"
                 : "=r"(r0), "=r"(r1), "=r"(r2), "=r"(r3) : "r"(addr));
}
__device__ __forceinline__ void ldsm_x4_t(uint32_t& r0, uint32_t& r1, uint32_t& r2, uint32_t& r3,
                                          uint32_t addr) {
    asm volatile("ldmatrix.sync.aligned.m8n8.x4.trans.shared.b16 {%0,%1,%2,%3}, [%4];"
                 : "=r"(r0), "=r"(r1), "=r"(r2), "=r"(r3) : "r"(addr));
}
__device__ __forceinline__ void mma_bf16(float* c, const uint32_t* a, const uint32_t* b) {
    asm volatile("mma.sync.aligned.m16n8k16.row.col.f32.bf16.bf16.f32 "
                 "{%0,%1,%2,%3}, {%4,%5,%6,%7}, {%8,%9}, {%0,%1,%2,%3};"
                 : "+f"(c[0]), "+f"(c[1]), "+f"(c[2]), "+f"(c[3])
                 : "r"(a[0]), "r"(a[1]), "r"(a[2]), "r"(a[3]), "r"(b[0]), "r"(b[1]));
}
__device__ __forceinline__ void bsplit(float x, __nv_bfloat16& h, __nv_bfloat16& l) {
    h = __float2bfloat16(x);
    l = __float2bfloat16(x - __bfloat162float(h));
}
__device__ __forceinline__ __nv_bfloat162 mk2(__nv_bfloat16 a, __nv_bfloat16 b) {
    __nv_bfloat162 v; v.x = a; v.y = b; return v;
}

// ------------------------- conversion kernels ------------------------------
__global__ __launch_bounds__(256)
void convE_kernel(const float* __restrict__ E) {
    int idx = blockIdx.x * 256 + threadIdx.x;   // over MT*D
    int row = idx >> 10, k = idx & 1023;
    __nv_bfloat16 h, l;
    bsplit(E[idx], h, l);
    __nv_bfloat16* p = g_Eext + (size_t)row * KE3;
    p[k] = h; p[D + k] = l; p[2 * D + k] = h;   // A-role [hi, lo, hi]
}

__global__ __launch_bounds__(256)
void convW_kernel(const float* __restrict__ Wk, const float* __restrict__ Wq,
                  const float* __restrict__ Wv) {
    const float* W = (blockIdx.z == 0) ? Wk : (blockIdx.z == 1) ? Wq : Wv;
    __nv_bfloat16* dst = g_WText + (size_t)blockIdx.z * D * KE3;
    __shared__ float tsm[32][33];
    int n0 = blockIdx.x * 32, k0 = blockIdx.y * 32;
    int tx = threadIdx.x, ty = threadIdx.y;
    #pragma unroll
    for (int i = 0; i < 4; i++)
        tsm[ty + 8 * i][tx] = W[(size_t)(k0 + ty + 8 * i) * D + n0 + tx];
    __syncthreads();
    #pragma unroll
    for (int i = 0; i < 4; i++) {
        int n = n0 + ty + 8 * i, k = k0 + tx;
        __nv_bfloat16 h, l;
        bsplit(tsm[tx][ty + 8 * i], h, l);       // = W[k][n]
        __nv_bfloat16* p = dst + (size_t)n * KE3;
        p[k] = h; p[D + k] = h; p[2 * D + k] = l;  // B-role [hi, hi, lo]
    }
}

// ------------------------- unified mma.sync GEMM ---------------------------
// MODE 0: qkv   out = E_ext @ WText[z]^T                grid (8, 64, 3)
// MODE 1: score S[b] = Q_ext @ K_ext^T (/32, causal)    grid (16, 16, 4)
// MODE 2: av    O[b] = S_ext @ V_ext (trans-B, bounded) grid (8, 16, 4)
template <int MODE>
__global__ __launch_bounds__(256, 2)
void gemm_mma(float* __restrict__ outp) {
    __shared__ __nv_bfloat16 As[2][STG_ELEMS];   // 2 x 10240 B
    __shared__ __nv_bfloat16 Bs[2][STG_ELEMS];   // 2 x 10240 B (mode2: 32*B2STR <= STG)

    const int tid = threadIdx.x;
    const int wid = tid >> 5, l = tid & 31;
    const int wm = wid & 1, wn = wid >> 1;          // 2(M) x 4(N) warp grid
    const int warpM = wm * 64, warpN = wn * 32;     // warp tile 64x32
    const int bx = blockIdx.x, by = blockIdx.y, bz = blockIdx.z;
    const int mBase = by * TM, nBase = bx * TN;

    const __nv_bfloat16 *Ag, *Bg;
    int ldk, nIter, nJ;
    if (MODE == 0) {
        Ag = g_Eext; Bg = g_WText + (size_t)bz * D * KE3;
        ldk = KE3; nJ = KE3 / BK; nIter = nJ;
    } else if (MODE == 1) {
        if (bx > by) return;                        // strictly above diagonal
        Ag = g_Qext + (size_t)bz * T * KE3;
        Bg = g_Kext + (size_t)bz * T * KE3;
        ldk = KE3; nJ = KE3 / BK; nIter = nJ;
    } else {
        Ag = g_Sext + (size_t)bz * T * (3 * T);
        Bg = g_Vext + (size_t)bz * (3 * T) * D;
        ldk = 3 * T;
        nJ = ((by + 1) * TM) / BK;                  // causal K bound per segment
        nIter = 3 * nJ;
    }

    float c[4][4][4] = {};
    uint4 pa[2], pb[2];

    // ---- global loaders (into registers) ----
    const int aRow = tid >> 2;                 // 0..63
    const int aKc  = (tid & 3) * 8;            // 0,8,16,24
    const int vRow = tid >> 4;                 // 0..15 (mode2 B k rows)
    const int vNc  = (tid & 15) * 8;           // 0..120

    auto kOff = [&](int it) -> int {
        if (MODE == 2) { int s = it / nJ; return s * T + (it - s * nJ) * BK; }
        return it * BK;
    };
    auto loadG = [&](int ko) {
        pa[0] = *(const uint4*)(Ag + (size_t)(mBase + aRow) * ldk + ko + aKc);
        pa[1] = *(const uint4*)(Ag + (size_t)(mBase + aRow + 64) * ldk + ko + aKc);
        if (MODE != 2) {
            pb[0] = *(const uint4*)(Bg + (size_t)(nBase + aRow) * ldk + ko + aKc);
            pb[1] = *(const uint4*)(Bg + (size_t)(nBase + aRow + 64) * ldk + ko + aKc);
        } else {
            pb[0] = *(const uint4*)(Bg + (size_t)(ko + vRow) * D + nBase + vNc);
            pb[1] = *(const uint4*)(Bg + (size_t)(ko + vRow + 16) * D + nBase + vNc);
        }
    };
    auto stsAll = [&](int buf) {
        __nv_bfloat16* sA = As[buf];
        __nv_bfloat16* sB = Bs[buf];
        *(uint4*)&sA[aRow * ASTR + aKc]        = pa[0];
        *(uint4*)&sA[(aRow + 64) * ASTR + aKc] = pa[1];
        if (MODE != 2) {
            *(uint4*)&sB[aRow * ASTR + aKc]        = pb[0];
            *(uint4*)&sB[(aRow + 64) * ASTR + aKc] = pb[1];
        } else {
            *(uint4*)&sB[vRow * B2STR + vNc]        = pb[0];
            *(uint4*)&sB[(vRow + 16) * B2STR + vNc] = pb[1];
        }
    };

    const uint32_t AsU = smem_u32(As), BsU = smem_u32(Bs);
    // lane-invariant ldmatrix addressing pieces
    const int aLR = (l & 15), aLC = (l >> 4) * 8;                       // A rows/k
    const int bLR = (l >> 4) * 8 + (l & 7), bLC = ((l >> 3) & 1) * 8;   // B[n][k]
    const int vLR = ((l >> 3) & 1) * 8 + (l & 7), vLC = (l >> 4) * 8;   // B[k][n] trans

    // ---- prologue: fill buffer 0 ----
    loadG(kOff(0));
    stsAll(0);
    __syncthreads();

    // ---- main loop: one barrier per iteration ----
    for (int it = 0; it < nIter; it++) {
        const int buf = it & 1;
        const bool more = (it + 1 < nIter);
        if (more) loadG(kOff(it + 1));   // long-latency LDG rides under the MMAs

        const uint32_t sAb = AsU + (buf * STG_ELEMS) * 2;
        const uint32_t sBb = BsU + (buf * STG_ELEMS) * 2;

        #pragma unroll
        for (int ks = 0; ks < 2; ks++) {
            uint32_t a[4][4], b[4][2];
            #pragma unroll
            for (int mi = 0; mi < 4; mi++)
                ldsm_x4(a[mi][0], a[mi][1], a[mi][2], a[mi][3],
                        sAb + ((warpM + mi * 16 + aLR) * ASTR + ks * 16 + aLC) * 2);
            if (MODE != 2) {
                #pragma unroll
                for (int n2 = 0; n2 < 4; n2 += 2)
                    ldsm_x4(b[n2][0], b[n2][1], b[n2 + 1][0], b[n2 + 1][1],
                            sBb + ((warpN + n2 * 8 + bLR) * ASTR + ks * 16 + bLC) * 2);
            } else {
                #pragma unroll
                for (int n2 = 0; n2 < 4; n2 += 2)
                    ldsm_x4_t(b[n2][0], b[n2][1], b[n2 + 1][0], b[n2 + 1][1],
                              sBb + ((ks * 16 + vLR) * B2STR + warpN + n2 * 8 + vLC) * 2);
            }
            #pragma unroll
            for (int mi = 0; mi < 4; mi++)
                #pragma unroll
                for (int ni = 0; ni < 4; ni++)
                    mma_bf16(c[mi][ni], a[mi], b[ni]);
        }

        if (more) {
            stsAll(buf ^ 1);     // other buffer: last read before previous barrier
            __syncthreads();     // single barrier per iteration
        }
    }

    // ---- epilogue (direct from accumulators) ----
    const int l4 = l >> 2, l2 = (l & 3) * 2;
    #pragma unroll
    for (int mi = 0; mi < 4; mi++) {
        #pragma unroll
        for (int ni = 0; ni < 4; ni++) {
            const int n = nBase + warpN + ni * 8 + l2;
            #pragma unroll
            for (int half = 0; half < 2; half++) {
                const int m = mBase + warpM + mi * 16 + l4 + half * 8;
                float v0 = c[mi][ni][half * 2 + 0];
                float v1 = c[mi][ni][half * 2 + 1];
                if (MODE == 0) {
                    __nv_bfloat16 h0, l0, h1, l1;
                    bsplit(v0, h0, l0); bsplit(v1, h1, l1);
                    if (bz == 1) {        // Q: A-role [hi, lo, hi]
                        __nv_bfloat16* p = g_Qext + (size_t)m * KE3;
                        *(__nv_bfloat162*)(p + n)         = mk2(h0, h1);
                        *(__nv_bfloat162*)(p + D + n)     = mk2(l0, l1);
                        *(__nv_bfloat162*)(p + 2 * D + n) = mk2(h0, h1);
                    } else if (bz == 0) { // K: B-role [hi, hi, lo]
                        __nv_bfloat16* p = g_Kext + (size_t)m * KE3;
                        *(__nv_bfloat162*)(p + n)         = mk2(h0, h1);
                        *(__nv_bfloat162*)(p + D + n)     = mk2(h0, h1);
                        *(__nv_bfloat162*)(p + 2 * D + n) = mk2(l0, l1);
                    } else {              // V: [b][seg][t][d], segs [hi, hi, lo]
                        int bb = m >> 11, t = m & (T - 1);
                        __nv_bfloat16* p = g_Vext + (size_t)bb * 3 * T * D;
                        *(__nv_bfloat162*)(p + (size_t)t * D + n)           = mk2(h0, h1);
                        *(__nv_bfloat162*)(p + (size_t)(T + t) * D + n)     = mk2(h0, h1);
                        *(__nv_bfloat162*)(p + (size_t)(2 * T + t) * D + n) = mk2(l0, l1);
                    }
                } else if (MODE == 1) {
                    float s0 = (n     > m) ? -INFINITY : v0 * 0.03125f;
                    float s1 = (n + 1 > m) ? -INFINITY : v1 * 0.03125f;
                    float* p = g_S + (size_t)bz * T * T + (size_t)m * T + n;
                    p[0] = s0; p[1] = s1;
                } else {
                    float* p = outp + (size_t)bz * T * D + (size_t)m * D + n;
                    p[0] = rintf(v0 * 10000.0f) * 1.0e-4f;
                    p[1] = rintf(v1 * 10000.0f) * 1.0e-4f;
                }
            }
        }
    }
}

// ------------------------- softmax -> split bf16 ---------------------------
__global__ __launch_bounds__(256)
void softmax_kernel() {
    const int r = blockIdx.x;
    const int b = r >> 11, t = r & (T - 1);
    float* row = g_S + (size_t)b * T * T + (size_t)t * T;
    __nv_bfloat16* orow = g_Sext + ((size_t)b * T + t) * (3 * T);
    const int L = ((t >> 7) + 1) << 7;   // ceil to 128-tile

    __shared__ float red[256];
    const int tid = threadIdx.x;

    float m = -INFINITY;
    for (int j = tid; j < L; j += 256) m = fmaxf(m, row[j]);
    red[tid] = m;
    __syncthreads();
    #pragma unroll
    for (int s = 128; s > 0; s >>= 1) {
        if (tid < s) red[tid] = fmaxf(red[tid], red[tid + s]);
        __syncthreads();
    }
    m = red[0];
    __syncthreads();

    float sum = 0.0f;
    for (int j = tid; j < L; j += 256) {
        float e = __expf(row[j] - m);   // exp(-inf)=0 handles the causal mask
        row[j] = e;
        sum += e;
    }
    red[tid] = sum;
    __syncthreads();
    #pragma unroll
    for (int s = 128; s > 0; s >>= 1) {
        if (tid < s) red[tid] += red[tid + s];
        __syncthreads();
    }
    const float inv = 1.0f / red[0];
    __syncthreads();

    for (int j = tid; j < L; j += 256) {
        float w = row[j] * inv;
        __nv_bfloat16 h, l;
        bsplit(w, h, l);
        orow[j] = h; orow[T + j] = l; orow[2 * T + j] = h;   // A-role [hi, lo, hi]
    }
}

// ---------------------------------------------------------------------------
extern "C" void kernel_launch(void* const* d_in, const int* in_sizes, int n_in,
                              void* d_out, int out_size) {
    const float* E  = (const float*)d_in[0];
    const float* Wk = (const float*)d_in[1];
    const float* Wq = (const float*)d_in[2];
    const float* Wv = (const float*)d_in[3];
    float* O = (float*)d_out;

    convE_kernel<<<(MT * D) / 256, 256>>>(E);
    convW_kernel<<<dim3(32, 32, 3), dim3(32, 8)>>>(Wk, Wq, Wv);
    gemm_mma<0><<<dim3(D / TN, MT / TM, 3), 256>>>(O);
    gemm_mma<1><<<dim3(T / TN, T / TM, BATCH), 256>>>(O);
    softmax_kernel<<<MT, 256>>>();
    gemm_mma<2><<<dim3(D / TN, T / TM, BATCH), 256>>>(O);
}

// round 11
// speedup vs baseline: 1.7246x; 1.1534x over previous
#include <cuda_runtime.h>
#include <cuda_bf16.h>
#include <stdint.h>
#include <stddef.h>
#include <math.h>

#define BATCH 4
#define T     2048
#define D     1024
#define MT    (BATCH * T)   // 8192

// CTA tile 128x128, 8 warps (2M x 4N), warp tile 64x32, base-K chunk = 16
#define TM 128
#define TN 128
#define BKB 16
#define AS16 24      // 16 + 8 pad (elems): 48B rows -> 16B-aligned, conflict-free ldsm
#define B2STR 136    // 128 + 8 pad (elems): 272B rows (16B-aligned) for [k][n] V tiles
#define TILE_ELEMS (TM * AS16)   // 3072 elems = 6144 B per tile (mode2 B: 16*136=2176 fits)

// ------------------------- device scratch (hi/lo pairs) --------------------
__device__ __nv_bfloat16 g_Eh[(size_t)MT * D],  g_El[(size_t)MT * D];
__device__ __nv_bfloat16 g_WTh[(size_t)3 * D * D], g_WTl[(size_t)3 * D * D]; // [z][n][k]
__device__ __nv_bfloat16 g_Qh[(size_t)MT * D],  g_Ql[(size_t)MT * D];
__device__ __nv_bfloat16 g_Kh[(size_t)MT * D],  g_Kl[(size_t)MT * D];
__device__ __nv_bfloat16 g_Vh[(size_t)MT * D],  g_Vl[(size_t)MT * D];       // [b][t][d]
__device__ float         g_S[(size_t)BATCH * T * T];                         // fp32 scores
__device__ __nv_bfloat16 g_Sh[(size_t)BATCH * T * T], g_Sl[(size_t)BATCH * T * T];

// ------------------------- helpers ------------------------------------
__device__ __forceinline__ uint32_t smem_u32(const void* p) {
    uint32_t a;
    asm("{ .reg .u64 t; cvta.to.shared.u64 t, %1; cvt.u32.u64 %0, t; }" : "=r"(a) : "l"(p));
    return a;
}
__device__ __forceinline__ void ldsm_x4(uint32_t& r0, uint32_t& r1, uint32_t& r2, uint32_t& r3,
                                        uint32_t addr) {
    asm volatile("ldmatrix.sync.aligned.m8n8.x4.shared.b16 {%0,%1,%2,%3}, [%4];"
                 : "=r"(r0), "=r"(r1), "=r"(r2), "=r"(r3) : "r"(addr));
}
__device__ __forceinline__ void ldsm_x4_t(uint32_t& r0, uint32_t& r1, uint32_t& r2, uint32_t& r3,
                                          uint32_t addr) {
    asm volatile("ldmatrix.sync.aligned.m8n8.x4.trans.shared.b16 {%0,%1,%2,%3}, [%4];"
                 : "=r"(r0), "=r"(r1), "=r"(r2), "=r"(r3) : "r"(addr));
}
__device__ __forceinline__ void mma_bf16(float* c, const uint32_t* a, const uint32_t* b) {
    asm volatile("mma.sync.aligned.m16n8k16.row.col.f32.bf16.bf16.f32 "
                 "{%0,%1,%2,%3}, {%4,%5,%6,%7}, {%8,%9}, {%0,%1,%2,%3};"
                 : "+f"(c[0]), "+f"(c[1]), "+f"(c[2]), "+f"(c[3])
                 : "r"(a[0]), "r"(a[1]), "r"(a[2]), "r"(a[3]), "r"(b[0]), "r"(b[1]));
}
__device__ __forceinline__ void bsplit(float x, __nv_bfloat16& h, __nv_bfloat16& l) {
    h = __float2bfloat16(x);
    l = __float2bfloat16(x - __bfloat162float(h));
}
__device__ __forceinline__ __nv_bfloat162 mk2(__nv_bfloat16 a, __nv_bfloat16 b) {
    __nv_bfloat162 v; v.x = a; v.y = b; return v;
}

// ------------------------- conversion kernels ------------------------------
__global__ __launch_bounds__(256)
void convE_kernel(const float* __restrict__ E) {
    int idx = blockIdx.x * 256 + threadIdx.x;   // over MT*D
    __nv_bfloat16 h, l;
    bsplit(E[idx], h, l);
    g_Eh[idx] = h; g_El[idx] = l;
}

__global__ __launch_bounds__(256)
void convW_kernel(const float* __restrict__ Wk, const float* __restrict__ Wq,
                  const float* __restrict__ Wv) {
    const float* W = (blockIdx.z == 0) ? Wk : (blockIdx.z == 1) ? Wq : Wv;
    const size_t zoff = (size_t)blockIdx.z * D * D;
    __shared__ float tsm[32][33];
    int n0 = blockIdx.x * 32, k0 = blockIdx.y * 32;
    int tx = threadIdx.x, ty = threadIdx.y;
    #pragma unroll
    for (int i = 0; i < 4; i++)
        tsm[ty + 8 * i][tx] = W[(size_t)(k0 + ty + 8 * i) * D + n0 + tx];
    __syncthreads();
    #pragma unroll
    for (int i = 0; i < 4; i++) {
        int n = n0 + ty + 8 * i, k = k0 + tx;
        __nv_bfloat16 h, l;
        bsplit(tsm[tx][ty + 8 * i], h, l);       // = W[k][n]
        g_WTh[zoff + (size_t)n * D + k] = h;     // [n][k]
        g_WTl[zoff + (size_t)n * D + k] = l;
    }
}

// ------------------------- unified mma.sync GEMM ---------------------------
// 3-pass split-bf16: acc += Ah*Bh + Ah*Bl + Al*Bh  (exact products in fp32)
// MODE 0: qkv   out = E @ WT[z]^T                 grid (8, 64, 3), K=1024
// MODE 1: score S[b] = Q @ K^T (/32, causal)      grid (16, 16, 4), K=1024
// MODE 2: av    O[b] = S @ V (trans-B, bounded)   grid (8, 16, 4),  K<=2048
template <int MODE>
__global__ __launch_bounds__(256, 2)
void gemm_mma(float* __restrict__ outp) {
    __shared__ __nv_bfloat16 sAh[2][TILE_ELEMS], sAl[2][TILE_ELEMS];
    __shared__ __nv_bfloat16 sBh[2][TILE_ELEMS], sBl[2][TILE_ELEMS];   // 48 KB total

    const int tid = threadIdx.x;
    const int wid = tid >> 5, l = tid & 31;
    const int wm = wid & 1, wn = wid >> 1;          // 2(M) x 4(N) warp grid
    const int warpM = wm * 64, warpN = wn * 32;     // warp tile 64x32
    const int bx = blockIdx.x, by = blockIdx.y, bz = blockIdx.z;
    const int mBase = by * TM, nBase = bx * TN;

    const __nv_bfloat16 *Agh, *Agl, *Bgh, *Bgl;
    int ldkA, nIter;
    if (MODE == 0) {
        Agh = g_Eh; Agl = g_El;
        Bgh = g_WTh + (size_t)bz * D * D; Bgl = g_WTl + (size_t)bz * D * D;
        ldkA = D; nIter = D / BKB;
    } else if (MODE == 1) {
        if (bx > by) return;                        // strictly above diagonal
        Agh = g_Qh + (size_t)bz * T * D; Agl = g_Ql + (size_t)bz * T * D;
        Bgh = g_Kh + (size_t)bz * T * D; Bgl = g_Kl + (size_t)bz * T * D;
        ldkA = D; nIter = D / BKB;
    } else {
        Agh = g_Sh + (size_t)bz * T * T; Agl = g_Sl + (size_t)bz * T * T;
        Bgh = g_Vh + (size_t)bz * T * D; Bgl = g_Vl + (size_t)bz * T * D;
        ldkA = T; nIter = ((by + 1) * TM) / BKB;    // causal K bound
    }

    float c[4][4][4] = {};
    uint4 pt[4];

    // ---- global loader (into registers); one 16B chunk per thread per tile ----
    // A tiles: 128 rows x 16 k = 256 chunks; row = tid>>1, chunk = (tid&1)*8 elems
    const int aRow = tid >> 1;
    const int aKc  = (tid & 1) * 8;
    // mode2 B tile: 16 k-rows x 128 n = 256 chunks; row = tid>>4, col = (tid&15)*8
    const int vRow = tid >> 4;
    const int vNc  = (tid & 15) * 8;

    auto loadG = [&](int ko) {
        const size_t aoff = (size_t)(mBase + aRow) * ldkA + ko + aKc;
        pt[0] = *(const uint4*)(Agh + aoff);
        pt[1] = *(const uint4*)(Agl + aoff);
        if (MODE != 2) {
            const size_t boff = (size_t)(nBase + aRow) * D + ko + aKc;
            pt[2] = *(const uint4*)(Bgh + boff);
            pt[3] = *(const uint4*)(Bgl + boff);
        } else {
            const size_t boff = (size_t)(ko + vRow) * D + nBase + vNc;
            pt[2] = *(const uint4*)(Bgh + boff);
            pt[3] = *(const uint4*)(Bgl + boff);
        }
    };
    auto stsAll = [&](int buf) {
        *(uint4*)&sAh[buf][aRow * AS16 + aKc] = pt[0];
        *(uint4*)&sAl[buf][aRow * AS16 + aKc] = pt[1];
        if (MODE != 2) {
            *(uint4*)&sBh[buf][aRow * AS16 + aKc] = pt[2];
            *(uint4*)&sBl[buf][aRow * AS16 + aKc] = pt[3];
        } else {
            *(uint4*)&sBh[buf][vRow * B2STR + vNc] = pt[2];
            *(uint4*)&sBl[buf][vRow * B2STR + vNc] = pt[3];
        }
    };

    // lane-invariant ldsm addressing pieces
    const int aLR = (l & 15), aLC = (l >> 4) * 8;                       // A rows/k
    const int bLR = (l >> 4) * 8 + (l & 7), bLC = ((l >> 3) & 1) * 8;   // B[n][k]
    const int vLR = ((l >> 3) & 1) * 8 + (l & 7), vLC = (l >> 4) * 8;   // B[k][n] trans

    auto ldsmA = [&](uint32_t (&a)[4][4], const __nv_bfloat16* base) {
        const uint32_t u = smem_u32(base);
        #pragma unroll
        for (int mi = 0; mi < 4; mi++)
            ldsm_x4(a[mi][0], a[mi][1], a[mi][2], a[mi][3],
                    u + ((warpM + mi * 16 + aLR) * AS16 + aLC) * 2);
    };
    auto ldsmB = [&](uint32_t (&b)[4][2], const __nv_bfloat16* base) {
        const uint32_t u = smem_u32(base);
        if (MODE != 2) {
            #pragma unroll
            for (int n2 = 0; n2 < 4; n2 += 2)
                ldsm_x4(b[n2][0], b[n2][1], b[n2 + 1][0], b[n2 + 1][1],
                        u + ((warpN + n2 * 8 + bLR) * AS16 + bLC) * 2);
        } else {
            #pragma unroll
            for (int n2 = 0; n2 < 4; n2 += 2)
                ldsm_x4_t(b[n2][0], b[n2][1], b[n2 + 1][0], b[n2 + 1][1],
                          u + (vLR * B2STR + warpN + n2 * 8 + vLC) * 2);
        }
    };
    auto mmaAll = [&](uint32_t (&a)[4][4], uint32_t (&b)[4][2]) {
        #pragma unroll
        for (int mi = 0; mi < 4; mi++)
            #pragma unroll
            for (int ni = 0; ni < 4; ni++)
                mma_bf16(c[mi][ni], a[mi], b[ni]);
    };

    // ---- prologue: fill buffer 0 ----
    loadG(0);
    stsAll(0);
    __syncthreads();

    // ---- main loop: one barrier per iteration, 3 MMA passes per iter ----
    for (int it = 0; it < nIter; it++) {
        const int buf = it & 1;
        const bool more = (it + 1 < nIter);
        if (more) loadG((it + 1) * BKB);   // LDG latency rides under the MMAs

        uint32_t a[4][4], b[4][2];
        ldsmA(a, sAh[buf]);
        ldsmB(b, sBh[buf]);
        mmaAll(a, b);                      // Ah * Bh
        ldsmB(b, sBl[buf]);
        mmaAll(a, b);                      // Ah * Bl   (a held in regs)
        ldsmA(a, sAl[buf]);
        ldsmB(b, sBh[buf]);
        mmaAll(a, b);                      // Al * Bh

        if (more) {
            stsAll(buf ^ 1);               // other buffer; safe before barrier
            __syncthreads();
        }
    }

    // ---- epilogue (direct from accumulators) ----
    const int l4 = l >> 2, l2 = (l & 3) * 2;
    #pragma unroll
    for (int mi = 0; mi < 4; mi++) {
        #pragma unroll
        for (int ni = 0; ni < 4; ni++) {
            const int n = nBase + warpN + ni * 8 + l2;
            #pragma unroll
            for (int half = 0; half < 2; half++) {
                const int m = mBase + warpM + mi * 16 + l4 + half * 8;
                float v0 = c[mi][ni][half * 2 + 0];
                float v1 = c[mi][ni][half * 2 + 1];
                if (MODE == 0) {
                    __nv_bfloat16 h0, l0, h1, l1;
                    bsplit(v0, h0, l0); bsplit(v1, h1, l1);
                    const size_t off = (size_t)m * D + n;
                    if (bz == 1) {
                        *(__nv_bfloat162*)(g_Qh + off) = mk2(h0, h1);
                        *(__nv_bfloat162*)(g_Ql + off) = mk2(l0, l1);
                    } else if (bz == 0) {
                        *(__nv_bfloat162*)(g_Kh + off) = mk2(h0, h1);
                        *(__nv_bfloat162*)(g_Kl + off) = mk2(l0, l1);
                    } else {
                        *(__nv_bfloat162*)(g_Vh + off) = mk2(h0, h1);   // [b][t][d] natural
                        *(__nv_bfloat162*)(g_Vl + off) = mk2(l0, l1);
                    }
                } else if (MODE == 1) {
                    float s0 = (n     > m) ? -INFINITY : v0 * 0.03125f;
                    float s1 = (n + 1 > m) ? -INFINITY : v1 * 0.03125f;
                    float* p = g_S + (size_t)bz * T * T + (size_t)m * T + n;
                    p[0] = s0; p[1] = s1;
                } else {
                    float* p = outp + (size_t)bz * T * D + (size_t)m * D + n;
                    p[0] = rintf(v0 * 10000.0f) * 1.0e-4f;
                    p[1] = rintf(v1 * 10000.0f) * 1.0e-4f;
                }
            }
        }
    }
}

// ------------------------- softmax -> split bf16 ---------------------------
__global__ __launch_bounds__(256)
void softmax_kernel() {
    const int r = blockIdx.x;
    const int b = r >> 11, t = r & (T - 1);
    float* row = g_S + (size_t)b * T * T + (size_t)t * T;
    __nv_bfloat16* oh = g_Sh + ((size_t)b * T + t) * T;
    __nv_bfloat16* ol = g_Sl + ((size_t)b * T + t) * T;
    const int L = ((t >> 7) + 1) << 7;   // ceil to 128-tile

    __shared__ float red[256];
    const int tid = threadIdx.x;

    float m = -INFINITY;
    for (int j = tid; j < L; j += 256) m = fmaxf(m, row[j]);
    red[tid] = m;
    __syncthreads();
    #pragma unroll
    for (int s = 128; s > 0; s >>= 1) {
        if (tid < s) red[tid] = fmaxf(red[tid], red[tid + s]);
        __syncthreads();
    }
    m = red[0];
    __syncthreads();

    float sum = 0.0f;
    for (int j = tid; j < L; j += 256) {
        float e = __expf(row[j] - m);   // exp(-inf)=0 handles the causal mask
        row[j] = e;
        sum += e;
    }
    red[tid] = sum;
    __syncthreads();
    #pragma unroll
    for (int s = 128; s > 0; s >>= 1) {
        if (tid < s) red[tid] += red[tid + s];
        __syncthreads();
    }
    const float inv = 1.0f / red[0];
    __syncthreads();

    for (int j = tid; j < L; j += 256) {
        float w = row[j] * inv;
        __nv_bfloat16 h, ll;
        bsplit(w, h, ll);
        oh[j] = h; ol[j] = ll;
    }
}

// ---------------------------------------------------------------------------
extern "C" void kernel_launch(void* const* d_in, const int* in_sizes, int n_in,
                              void* d_out, int out_size) {
    const float* E  = (const float*)d_in[0];
    const float* Wk = (const float*)d_in[1];
    const float* Wq = (const float*)d_in[2];
    const float* Wv = (const float*)d_in[3];
    float* O = (float*)d_out;

    convE_kernel<<<(MT * D) / 256, 256>>>(E);
    convW_kernel<<<dim3(32, 32, 3), dim3(32, 8)>>>(Wk, Wq, Wv);
    gemm_mma<0><<<dim3(D / TN, MT / TM, 3), 256>>>(O);
    gemm_mma<1><<<dim3(T / TN, T / TM, BATCH), 256>>>(O);
    softmax_kernel<<<MT, 256>>>();
    gemm_mma<2><<<dim3(D / TN, T / TM, BATCH), 256>>>(O);
}

// round 12
// speedup vs baseline: 1.8805x; 1.0904x over previous
#include <cuda_runtime.h>
#include <cuda_bf16.h>
#include <stdint.h>
#include <stddef.h>
#include <math.h>

#define BATCH 4
#define T     2048
#define D     1024
#define MT    (BATCH * T)   // 8192

// CTA tile 128x128, 8 warps (2M x 4N), warp tile 64x32, base-K chunk = 16
#define TM 128
#define TN 128
#define BKB 16
// A/B (mode!=2) tiles: plane-split layout, 2 planes x 128 rows x 16B, plane1
// rotated by 64B -> conflict-free STS.128 AND conflict-free ldsm. 4096B/tile.
#define B2STR 136    // mode2 V tiles: 128+8 pad elems (272B rows), conflict-free

// ------------------------- device scratch (hi/lo pairs) --------------------
__device__ __nv_bfloat16 g_Eh[(size_t)MT * D],  g_El[(size_t)MT * D];
__device__ __nv_bfloat16 g_WTh[(size_t)3 * D * D], g_WTl[(size_t)3 * D * D]; // [z][n][k]
__device__ __nv_bfloat16 g_Qh[(size_t)MT * D],  g_Ql[(size_t)MT * D];
__device__ __nv_bfloat16 g_Kh[(size_t)MT * D],  g_Kl[(size_t)MT * D];
__device__ __nv_bfloat16 g_Vh[(size_t)MT * D],  g_Vl[(size_t)MT * D];       // [b][t][d]
__device__ float         g_S[(size_t)BATCH * T * T];                         // fp32 scores
__device__ __nv_bfloat16 g_Sh[(size_t)BATCH * T * T], g_Sl[(size_t)BATCH * T * T];

// ------------------------- helpers ------------------------------------
__device__ __forceinline__ uint32_t smem_u32(const void* p) {
    uint32_t a;
    asm("{ .reg .u64 t; cvta.to.shared.u64 t, %1; cvt.u32.u64 %0, t; }" : "=r"(a) : "l"(p));
    return a;
}
// byte offset of (row, k-half) 16B chunk inside a plane-split tile
__device__ __forceinline__ int pOff(int row, int half) {
    return half * 2048 + (((row << 4) + (half << 6)) & 2047);
}
__device__ __forceinline__ void ldsm_x4(uint32_t& r0, uint32_t& r1, uint32_t& r2, uint32_t& r3,
                                        uint32_t addr) {
    asm volatile("ldmatrix.sync.aligned.m8n8.x4.shared.b16 {%0,%1,%2,%3}, [%4];"
                 : "=r"(r0), "=r"(r1), "=r"(r2), "=r"(r3) : "r"(addr));
}
__device__ __forceinline__ void ldsm_x4_t(uint32_t& r0, uint32_t& r1, uint32_t& r2, uint32_t& r3,
                                          uint32_t addr) {
    asm volatile("ldmatrix.sync.aligned.m8n8.x4.trans.shared.b16 {%0,%1,%2,%3}, [%4];"
                 : "=r"(r0), "=r"(r1), "=r"(r2), "=r"(r3) : "r"(addr));
}
__device__ __forceinline__ void mma_bf16(float* c, const uint32_t* a, const uint32_t* b) {
    asm volatile("mma.sync.aligned.m16n8k16.row.col.f32.bf16.bf16.f32 "
                 "{%0,%1,%2,%3}, {%4,%5,%6,%7}, {%8,%9}, {%0,%1,%2,%3};"
                 : "+f"(c[0]), "+f"(c[1]), "+f"(c[2]), "+f"(c[3])
                 : "r"(a[0]), "r"(a[1]), "r"(a[2]), "r"(a[3]), "r"(b[0]), "r"(b[1]));
}
__device__ __forceinline__ void bsplit(float x, __nv_bfloat16& h, __nv_bfloat16& l) {
    h = __float2bfloat16(x);
    l = __float2bfloat16(x - __bfloat162float(h));
}
__device__ __forceinline__ __nv_bfloat162 mk2(__nv_bfloat16 a, __nv_bfloat16 b) {
    __nv_bfloat162 v; v.x = a; v.y = b; return v;
}

// ------------------------- conversion kernels ------------------------------
__global__ __launch_bounds__(256)
void convE_kernel(const float* __restrict__ E) {
    int idx = blockIdx.x * 256 + threadIdx.x;   // over MT*D
    __nv_bfloat16 h, l;
    bsplit(E[idx], h, l);
    g_Eh[idx] = h; g_El[idx] = l;
}

__global__ __launch_bounds__(256)
void convW_kernel(const float* __restrict__ Wk, const float* __restrict__ Wq,
                  const float* __restrict__ Wv) {
    const float* W = (blockIdx.z == 0) ? Wk : (blockIdx.z == 1) ? Wq : Wv;
    const size_t zoff = (size_t)blockIdx.z * D * D;
    __shared__ float tsm[32][33];
    int n0 = blockIdx.x * 32, k0 = blockIdx.y * 32;
    int tx = threadIdx.x, ty = threadIdx.y;
    #pragma unroll
    for (int i = 0; i < 4; i++)
        tsm[ty + 8 * i][tx] = W[(size_t)(k0 + ty + 8 * i) * D + n0 + tx];
    __syncthreads();
    #pragma unroll
    for (int i = 0; i < 4; i++) {
        int n = n0 + ty + 8 * i, k = k0 + tx;
        __nv_bfloat16 h, l;
        bsplit(tsm[tx][ty + 8 * i], h, l);       // = W[k][n]
        g_WTh[zoff + (size_t)n * D + k] = h;     // [n][k]
        g_WTl[zoff + (size_t)n * D + k] = l;
    }
}

// ------------------------- unified mma.sync GEMM ---------------------------
// 3-pass split-bf16: acc += Ah*Bh + Ah*Bl + Al*Bh  (exact products in fp32)
// MODE 0: qkv   out = E @ WT[z]^T                 grid (8, 64, 3), K=1024
// MODE 1: score S[b] = Q @ K^T (/32, causal)      grid (16, 16, 4), K=1024
// MODE 2: av    O[b] = S @ V (trans-B, bounded)   grid (8, 16, 4),  K<=2048
template <int MODE>
__global__ __launch_bounds__(256, 2)
void gemm_mma(float* __restrict__ outp) {
    // A tiles: 2048 elems (4096B, plane-split). B tiles: 2304 elems
    // (mode!=2 uses first 2048 plane-split; mode2 uses 16*B2STR=2176 padded).
    __shared__ __align__(128) __nv_bfloat16 sAh[2][2048], sAl[2][2048];
    __shared__ __align__(128) __nv_bfloat16 sBh[2][2304], sBl[2][2304];

    const int tid = threadIdx.x;
    const int wid = tid >> 5, l = tid & 31;
    const int wm = wid & 1, wn = wid >> 1;          // 2(M) x 4(N) warp grid
    const int warpM = wm * 64, warpN = wn * 32;     // warp tile 64x32
    const int bx = blockIdx.x, by = blockIdx.y, bz = blockIdx.z;
    const int mBase = by * TM, nBase = bx * TN;

    const __nv_bfloat16 *Agh, *Agl, *Bgh, *Bgl;
    int ldkA, nIter;
    if (MODE == 0) {
        Agh = g_Eh; Agl = g_El;
        Bgh = g_WTh + (size_t)bz * D * D; Bgl = g_WTl + (size_t)bz * D * D;
        ldkA = D; nIter = D / BKB;
    } else if (MODE == 1) {
        if (bx > by) return;                        // strictly above diagonal
        Agh = g_Qh + (size_t)bz * T * D; Agl = g_Ql + (size_t)bz * T * D;
        Bgh = g_Kh + (size_t)bz * T * D; Bgl = g_Kl + (size_t)bz * T * D;
        ldkA = D; nIter = D / BKB;
    } else {
        Agh = g_Sh + (size_t)bz * T * T; Agl = g_Sl + (size_t)bz * T * T;
        Bgh = g_Vh + (size_t)bz * T * D; Bgl = g_Vl + (size_t)bz * T * D;
        ldkA = T; nIter = ((by + 1) * TM) / BKB;    // causal K bound
    }

    float c[4][4][4] = {};
    uint4 pt[4];

    // ---- global loader (into registers); one 16B chunk per thread per tile ----
    // A/B tiles: row = tid>>1 (0..127), k-half = tid&1  -> coalesced 32B/row
    const int aRow = tid >> 1;
    const int aHalf = tid & 1;
    const int aSts = pOff(aRow, aHalf);        // plane-split STS offset (bytes)
    // mode2 B tile: 16 k-rows x 128 n; row = tid>>4, col = (tid&15)*8 elems
    const int vRow = tid >> 4;
    const int vNc  = (tid & 15) * 8;

    auto loadG = [&](int ko) {
        const size_t aoff = (size_t)(mBase + aRow) * ldkA + ko + aHalf * 8;
        pt[0] = *(const uint4*)(Agh + aoff);
        pt[1] = *(const uint4*)(Agl + aoff);
        if (MODE != 2) {
            const size_t boff = (size_t)(nBase + aRow) * D + ko + aHalf * 8;
            pt[2] = *(const uint4*)(Bgh + boff);
            pt[3] = *(const uint4*)(Bgl + boff);
        } else {
            const size_t boff = (size_t)(ko + vRow) * D + nBase + vNc;
            pt[2] = *(const uint4*)(Bgh + boff);
            pt[3] = *(const uint4*)(Bgl + boff);
        }
    };
    auto stsAll = [&](int buf) {
        *(uint4*)((char*)sAh[buf] + aSts) = pt[0];
        *(uint4*)((char*)sAl[buf] + aSts) = pt[1];
        if (MODE != 2) {
            *(uint4*)((char*)sBh[buf] + aSts) = pt[2];
            *(uint4*)((char*)sBl[buf] + aSts) = pt[3];
        } else {
            *(uint4*)&sBh[buf][vRow * B2STR + vNc] = pt[2];
            *(uint4*)&sBl[buf][vRow * B2STR + vNc] = pt[3];
        }
    };

    // lane-invariant ldsm addressing pieces (plane-split layout)
    const int aPl = l >> 4;                         // A: plane select
    const int aRw = ((l >> 3) & 1) * 8 + (l & 7);   // A: row within 16-group
    const int bPl = (l >> 3) & 1;                   // B: plane select
    const int bRw = (l & 7) + (l >> 4) * 8;         // B: row within 16-group
    // mode2 trans ldsm pieces (padded [k][n] layout)
    const int vLR = ((l >> 3) & 1) * 8 + (l & 7), vLC = (l >> 4) * 8;

    auto ldsmA = [&](uint32_t (&a)[4][4], const __nv_bfloat16* base) {
        const uint32_t u = smem_u32(base);
        #pragma unroll
        for (int mi = 0; mi < 4; mi++)
            ldsm_x4(a[mi][0], a[mi][1], a[mi][2], a[mi][3],
                    u + pOff(warpM + mi * 16 + aRw, aPl));
    };
    auto ldsmB = [&](uint32_t (&b)[4][2], const __nv_bfloat16* base) {
        const uint32_t u = smem_u32(base);
        if (MODE != 2) {
            #pragma unroll
            for (int n2 = 0; n2 < 4; n2 += 2)
                ldsm_x4(b[n2][0], b[n2][1], b[n2 + 1][0], b[n2 + 1][1],
                        u + pOff(warpN + n2 * 8 + bRw, bPl));
        } else {
            #pragma unroll
            for (int n2 = 0; n2 < 4; n2 += 2)
                ldsm_x4_t(b[n2][0], b[n2][1], b[n2 + 1][0], b[n2 + 1][1],
                          u + (vLR * B2STR + warpN + n2 * 8 + vLC) * 2);
        }
    };
    auto mmaAll = [&](uint32_t (&a)[4][4], uint32_t (&b)[4][2]) {
        #pragma unroll
        for (int mi = 0; mi < 4; mi++)
            #pragma unroll
            for (int ni = 0; ni < 4; ni++)
                mma_bf16(c[mi][ni], a[mi], b[ni]);
    };

    // ---- prologue: fill buffer 0 ----
    loadG(0);
    stsAll(0);
    __syncthreads();

    // ---- main loop: one barrier per iteration, 3 MMA passes per iter ----
    for (int it = 0; it < nIter; it++) {
        const int buf = it & 1;
        const bool more = (it + 1 < nIter);
        if (more) loadG((it + 1) * BKB);   // LDG latency rides under the MMAs

        uint32_t a[4][4], b[4][2];
        ldsmA(a, sAh[buf]);
        ldsmB(b, sBh[buf]);
        mmaAll(a, b);                      // Ah * Bh
        ldsmB(b, sBl[buf]);
        mmaAll(a, b);                      // Ah * Bl   (a held in regs)
        ldsmA(a, sAl[buf]);
        ldsmB(b, sBh[buf]);
        mmaAll(a, b);                      // Al * Bh

        if (more) {
            stsAll(buf ^ 1);               // other buffer; safe before barrier
            __syncthreads();
        }
    }

    // ---- epilogue (direct from accumulators) ----
    const int l4 = l >> 2, l2 = (l & 3) * 2;
    #pragma unroll
    for (int mi = 0; mi < 4; mi++) {
        #pragma unroll
        for (int ni = 0; ni < 4; ni++) {
            const int n = nBase + warpN + ni * 8 + l2;
            #pragma unroll
            for (int half = 0; half < 2; half++) {
                const int m = mBase + warpM + mi * 16 + l4 + half * 8;
                float v0 = c[mi][ni][half * 2 + 0];
                float v1 = c[mi][ni][half * 2 + 1];
                if (MODE == 0) {
                    __nv_bfloat16 h0, l0, h1, l1;
                    bsplit(v0, h0, l0); bsplit(v1, h1, l1);
                    const size_t off = (size_t)m * D + n;
                    if (bz == 1) {
                        *(__nv_bfloat162*)(g_Qh + off) = mk2(h0, h1);
                        *(__nv_bfloat162*)(g_Ql + off) = mk2(l0, l1);
                    } else if (bz == 0) {
                        *(__nv_bfloat162*)(g_Kh + off) = mk2(h0, h1);
                        *(__nv_bfloat162*)(g_Kl + off) = mk2(l0, l1);
                    } else {
                        *(__nv_bfloat162*)(g_Vh + off) = mk2(h0, h1);   // [b][t][d]
                        *(__nv_bfloat162*)(g_Vl + off) = mk2(l0, l1);
                    }
                } else if (MODE == 1) {
                    float s0 = (n     > m) ? -INFINITY : v0 * 0.03125f;
                    float s1 = (n + 1 > m) ? -INFINITY : v1 * 0.03125f;
                    float* p = g_S + (size_t)bz * T * T + (size_t)m * T + n;
                    p[0] = s0; p[1] = s1;
                } else {
                    float* p = outp + (size_t)bz * T * D + (size_t)m * D + n;
                    p[0] = rintf(v0 * 10000.0f) * 1.0e-4f;
                    p[1] = rintf(v1 * 10000.0f) * 1.0e-4f;
                }
            }
        }
    }
}

// ------------------------- softmax -> split bf16 ---------------------------
__global__ __launch_bounds__(256)
void softmax_kernel() {
    const int r = blockIdx.x;
    const int b = r >> 11, t = r & (T - 1);
    float* row = g_S + (size_t)b * T * T + (size_t)t * T;
    __nv_bfloat16* oh = g_Sh + ((size_t)b * T + t) * T;
    __nv_bfloat16* ol = g_Sl + ((size_t)b * T + t) * T;
    const int L = ((t >> 7) + 1) << 7;   // ceil to 128-tile

    __shared__ float red[256];
    const int tid = threadIdx.x;

    float m = -INFINITY;
    for (int j = tid; j < L; j += 256) m = fmaxf(m, row[j]);
    red[tid] = m;
    __syncthreads();
    #pragma unroll
    for (int s = 128; s > 0; s >>= 1) {
        if (tid < s) red[tid] = fmaxf(red[tid], red[tid + s]);
        __syncthreads();
    }
    m = red[0];
    __syncthreads();

    float sum = 0.0f;
    for (int j = tid; j < L; j += 256) {
        float e = __expf(row[j] - m);   // exp(-inf)=0 handles the causal mask
        row[j] = e;
        sum += e;
    }
    red[tid] = sum;
    __syncthreads();
    #pragma unroll
    for (int s = 128; s > 0; s >>= 1) {
        if (tid < s) red[tid] += red[tid + s];
        __syncthreads();
    }
    const float inv = 1.0f / red[0];
    __syncthreads();

    for (int j = tid; j < L; j += 256) {
        float w = row[j] * inv;
        __nv_bfloat16 h, ll;
        bsplit(w, h, ll);
        oh[j] = h; ol[j] = ll;
    }
}

// ---------------------------------------------------------------------------
extern "C" void kernel_launch(void* const* d_in, const int* in_sizes, int n_in,
                              void* d_out, int out_size) {
    const float* E  = (const float*)d_in[0];
    const float* Wk = (const float*)d_in[1];
    const float* Wq = (const float*)d_in[2];
    const float* Wv = (const float*)d_in[3];
    float* O = (float*)d_out;

    convE_kernel<<<(MT * D) / 256, 256>>>(E);
    convW_kernel<<<dim3(32, 32, 3), dim3(32, 8)>>>(Wk, Wq, Wv);
    gemm_mma<0><<<dim3(D / TN, MT / TM, 3), 256>>>(O);
    gemm_mma<1><<<dim3(T / TN, T / TM, BATCH), 256>>>(O);
    softmax_kernel<<<MT, 256>>>();
    gemm_mma<2><<<dim3(D / TN, T / TM, BATCH), 256>>>(O);
}